// round 16
// baseline (speedup 1.0000x reference)
#include <cuda_runtime.h>
#include <cstdint>
#include <cstddef>

#define H 512
#define W 512
#define C 128
#define TI 16
#define TJ 16
// x halo (fp32): [8 chg][23 rows][25 colpad][4 ch] floats; position = 16 B.
// XROW = 25*4 = 100 (== 4 mod 32), XCHUNK = 23*100 = 2300 (== 28 mod 32).
// Warp = 8 chg x 4 rows; LDS.128 start bank = 4*(7*chg + row) mod 32 ->
// each 4-bank group hit by exactly 4 lanes: 512 B in the minimum 4 wavefronts.
#define XROW 100
#define XCHUNK 2300
#define XS_F (8 * XCHUNK)                 // 18400 floats
#define SMEM_FLOATS (XS_F + 529 + 256)    // 19185
#define SMEM_BYTES (SMEM_FLOATS * 4)      // 76,740 B -> 2 CTAs/SM

typedef unsigned long long ull;

__device__ __forceinline__ ull pack2(float a, float b) {
    ull r; asm("mov.b64 %0, {%1, %2};" : "=l"(r) : "f"(a), "f"(b)); return r;
}
__device__ __forceinline__ void fma2(ull& d, ull a, ull b) {
    asm("fma.rn.f32x2 %0, %1, %2, %0;" : "+l"(d) : "l"(a), "l"(b));
}
__device__ __forceinline__ float2 unpack2(ull v) {
    float2 f; asm("mov.b64 {%0, %1}, %2;" : "=f"(f.x), "=f"(f.y) : "l"(v)); return f;
}
__device__ __forceinline__ void cp_async16(float* smem_dst, const float* gsrc, bool pred) {
    uint32_t s = (uint32_t)__cvta_generic_to_shared(smem_dst);
    int sz = pred ? 16 : 0;
    asm volatile("cp.async.cg.shared.global [%0], [%1], 16, %2;\n"
                 :: "r"(s), "l"(gsrc), "r"(sz));
}
__device__ __forceinline__ void cp_async4(float* smem_dst, const float* gsrc, bool pred) {
    uint32_t s = (uint32_t)__cvta_generic_to_shared(smem_dst);
    int sz = pred ? 4 : 0;
    asm volatile("cp.async.ca.shared.global [%0], [%1], 4, %2;\n"
                 :: "r"(s), "l"(gsrc), "r"(sz));
}
__device__ __forceinline__ void cp_commit() {
    asm volatile("cp.async.commit_group;\n" ::: "memory");
}
template <int N> __device__ __forceinline__ void cp_wait() {
    asm volatile("cp.async.wait_group %0;\n" :: "n"(N) : "memory");
}

// ---- stage one 32-channel x pass straight into smem via cp.async ----
// 8 consecutive lanes cover one pixel's 32 channels (128 B contiguous gmem).
__device__ __forceinline__ void stage_x(float* xs, const float* __restrict__ gx,
                                        int bi, int bj, int pass, int tid) {
    const int cbase = pass * 32;
    #pragma unroll 4
    for (int u = tid; u < 529 * 8; u += 256) {
        int q = u & 7, pix = u >> 3;
        int hr = pix / 23, hc = pix - hr * 23;
        int gr = bi + hr - 3, gcl = bj + hc - 3;
        bool ok = ((unsigned)gr < H) && ((unsigned)gcl < W);
        const float* src = ok
            ? gx + (((size_t)gr * W + gcl) * C + cbase + q * 4)
            : gx;
        cp_async16(xs + q * XCHUNK + hr * XROW + hc * 4, src, ok);
    }
}

// ---- compute one pass: 1 row x 8 cols x 4 ch; weights streamed from L1/L2 ----
__device__ __forceinline__ void compute_pass(const float* __restrict__ xs,
                                             const float* __restrict__ gw,
                                             const float* __restrict__ inv,
                                             float* __restrict__ gout,
                                             int bi, int bj, int cbase,
                                             int row, int j0, int chg) {
    ull acc[8][2];
    #pragma unroll
    for (int j = 0; j < 8; ++j) { acc[j][0] = 0ull; acc[j][1] = 0ull; }

    const float* xb = xs + chg * XCHUNK + j0 * 4;
    // weights for this thread's 8 output pixels (row, j0..j0+7), global memory
    const float* wg = gw + ((size_t)(bi + row) * W + (bj + j0)) * 64;

    #pragma unroll
    for (int p = 0; p < 8; ++p) {
        // 15-position halo row: LDS.128 each, directly f32x2-ready (NO cvt)
        ull xf[15][2];
        const ulonglong2* xp = (const ulonglong2*)(xb + (row + p) * XROW);
        #pragma unroll
        for (int t = 0; t < 15; ++t) {
            ulonglong2 v = xp[t];
            xf[t][0] = v.x; xf[t][1] = v.y;
        }
        #pragma unroll
        for (int j = 0; j < 8; ++j) {
            #pragma unroll
            for (int qg = 0; qg < 2; ++qg) {
                float4 w4 = *(const float4*)(wg + j * 64 + p * 8 + qg * 4);
                const int t0 = j + qg * 4;
                ull w0 = pack2(w4.x, w4.x);
                ull w1 = pack2(w4.y, w4.y);
                ull w2 = pack2(w4.z, w4.z);
                ull w3p = pack2(w4.w, w4.w);
                fma2(acc[j][0], xf[t0 + 0][0], w0);
                fma2(acc[j][1], xf[t0 + 0][1], w0);
                fma2(acc[j][0], xf[t0 + 1][0], w1);
                fma2(acc[j][1], xf[t0 + 1][1], w1);
                fma2(acc[j][0], xf[t0 + 2][0], w2);
                fma2(acc[j][1], xf[t0 + 2][1], w2);
                fma2(acc[j][0], xf[t0 + 3][0], w3p);
                fma2(acc[j][1], xf[t0 + 3][1], w3p);
            }
        }
    }

    // ---- normalize + store (8 chg lanes -> 128 B contiguous per (row,j)) ----
    #pragma unroll
    for (int j = 0; j < 8; ++j) {
        float s = inv[row * 16 + j0 + j];
        float2 a0 = unpack2(acc[j][0]);
        float2 a1 = unpack2(acc[j][1]);
        float4 v = make_float4(a0.x * s, a0.y * s, a1.x * s, a1.y * s);
        *(float4*)(gout + (((size_t)(bi + row) * W + (bj + j0 + j)) * C
                           + cbase + chg * 4)) = v;
    }
}

__global__ __launch_bounds__(256, 2) void cell_att_kernel(
    const float* __restrict__ gx,   // [H][W][C]
    const float* __restrict__ gw,   // [H][W][64]
    const float* __restrict__ gc,   // [H][W]
    float* __restrict__ gout)       // [H][W][C]
{
    extern __shared__ float smem[];
    float* xs  = smem;               // fp32 x halo (32 ch per pass)
    float* ch  = xs + XS_F;          // 23x23 cnts halo
    float* inv = ch + 529;           // 256 per-pixel 1/(tcnt+1e-6)

    const int tid = threadIdx.x;
    const int chg = tid & 7;            // channel quad (4 ch)
    const int row = (tid >> 3) & 15;    // 0..15
    const int jg  = tid >> 7;           // 0 or 1
    const int j0  = jg * 8;
    const int bi = blockIdx.y * TI, bj = blockIdx.x * TJ;

    // ---- stage cnts halo + x pass 0 (one cp.async group) ----
    for (int u = tid; u < 529; u += 256) {
        int hr = u / 23, hc = u - hr * 23;
        int gr = bi + hr - 3, gcl = bj + hc - 3;
        bool ok = ((unsigned)gr < H) && ((unsigned)gcl < W);
        const float* src = ok ? gc + (size_t)gr * W + gcl : gc;
        cp_async4(ch + u, src, ok);
    }
    stage_x(xs, gx, bi, bj, 0, tid);
    cp_commit();
    cp_wait<0>();
    __syncthreads();                    // ch + xs(pass0) visible

    // ---- normalizer: inv = 1/(att(cnts)+1e-6), one pixel per thread ----
    // weights read straight from gmem (warms L1/L2 for the compute passes)
    {
        int il = tid >> 4, jl = tid & 15;
        const float* wpx = gw + ((size_t)(bi + il) * W + (bj + jl)) * 64;
        float s = 0.f;
        #pragma unroll
        for (int t4 = 0; t4 < 16; ++t4) {
            float4 w4 = *(const float4*)(wpx + t4 * 4);
            int p0 = (t4 * 4) >> 3, q0 = (t4 * 4) & 7;
            // taps t4*4 .. t4*4+3 are contiguous in q (q0..q0+3, same p row)
            const float* crow = ch + (il + p0) * 23 + jl;
            s += crow[q0 + 0] * w4.x;
            s += crow[q0 + 1] * w4.y;
            s += crow[q0 + 2] * w4.z;
            s += crow[q0 + 3] * w4.w;
        }
        inv[tid] = 1.0f / (s + 1e-6f);
    }
    __syncthreads();                    // inv visible

    compute_pass(xs, gw, inv, gout, bi, bj, 0, row, j0, chg);

    #pragma unroll 1
    for (int pass = 1; pass < 4; ++pass) {
        __syncthreads();                // everyone done reading xs
        stage_x(xs, gx, bi, bj, pass, tid);
        cp_commit();
        cp_wait<0>();
        __syncthreads();                // new xs visible
        compute_pass(xs, gw, inv, gout, bi, bj, pass * 32, row, j0, chg);
    }
}

extern "C" void kernel_launch(void* const* d_in, const int* in_sizes, int n_in,
                              void* d_out, int out_size) {
    const float* x0 = (const float*)d_in[0];
    const float* w  = (const float*)d_in[1];
    const float* c  = (const float*)d_in[2];
    float* out      = (float*)d_out;
    cudaFuncSetAttribute(cell_att_kernel,
                         cudaFuncAttributeMaxDynamicSharedMemorySize, SMEM_BYTES);
    dim3 grid(W / TJ, H / TI);
    cell_att_kernel<<<grid, 256, SMEM_BYTES>>>(x0, w, c, out);
}

// round 17
// speedup vs baseline: 3.2411x; 3.2411x over previous
#include <cuda_runtime.h>
#include <cuda_fp16.h>
#include <cstdint>
#include <cstddef>

#define H 512
#define W 512
#define C 128
#define TI 32
#define TJ 16
#define HR 39                               // TI + 7 halo rows
#define HC 23                               // TJ + 7 halo cols
// weights smem: [32 i][16 j][64 t] fp32, i-stride 1028 (== 4 mod 32):
// 4 row-lanes at bank groups {0,4,8,12}+c, chg lanes broadcast.
#define WISTRIDE 1028
#define W3_FLOATS (32 * WISTRIDE)           // 32896
// x halo (fp16): [8 chg][39 rows][24 colpad][4 ch]; 4 fp16 = 8 B = 2 u32.
// row stride 48 u32; chunk 39*48 = 1872 -> pad 1874 (== 18 mod 32, same
// residue as the verified R15 layout: warp 8 chg x 4 rows covers all 32
// banks with 2 requests each -> 256 B warp access in minimum 2 wavefronts).
#define XROWU 48
#define XCHUNK2 1874
#define XS_U32 (8 * XCHUNK2)                // 14992
#define SMEM_FLOATS (W3_FLOATS + XS_U32 + HR * HC + 512)
#define SMEM_BYTES (SMEM_FLOATS * 4)        // 197,184 B -> 1 CTA, 16 warps

typedef unsigned long long ull;

__device__ __forceinline__ ull pack2(float a, float b) {
    ull r; asm("mov.b64 %0, {%1, %2};" : "=l"(r) : "f"(a), "f"(b)); return r;
}
__device__ __forceinline__ void fma2(ull& d, ull a, ull b) {
    asm("fma.rn.f32x2 %0, %1, %2, %0;" : "+l"(d) : "l"(a), "l"(b));
}
__device__ __forceinline__ float2 unpack2(ull v) {
    float2 f; asm("mov.b64 {%0, %1}, %2;" : "=f"(f.x), "=f"(f.y) : "l"(v)); return f;
}
__device__ __forceinline__ void cp_async16(float* smem_dst, const float* gsrc) {
    uint32_t s = (uint32_t)__cvta_generic_to_shared(smem_dst);
    asm volatile("cp.async.cg.shared.global [%0], [%1], 16;\n"
                 :: "r"(s), "l"(gsrc));
}
__device__ __forceinline__ void cp_async4(float* smem_dst, const float* gsrc, bool pred) {
    uint32_t s = (uint32_t)__cvta_generic_to_shared(smem_dst);
    int sz = pred ? 4 : 0;
    asm volatile("cp.async.ca.shared.global [%0], [%1], 4, %2;\n"
                 :: "r"(s), "l"(gsrc), "r"(sz));
}
__device__ __forceinline__ void cp_commit() {
    asm volatile("cp.async.commit_group;\n" ::: "memory");
}
template <int N> __device__ __forceinline__ void cp_wait() {
    asm volatile("cp.async.wait_group %0;\n" :: "n"(N) : "memory");
}

// ---- stage one 32-channel x pass: LDG fp32 -> cvt fp16 -> STS (8 B) ----
// 8 consecutive lanes read one pixel's 32 channels (128 B contiguous gmem).
__device__ __forceinline__ void stage_x(uint32_t* xs2, const float* __restrict__ gx,
                                        int bi, int bj, int pass, int tid) {
    const int cbase = pass * 32;
    #pragma unroll 4
    for (int u = tid; u < HR * HC * 8; u += 512) {
        int q = u & 7, pix = u >> 3;
        int hr = pix / HC, hc = pix - hr * HC;
        int gr = bi + hr - 3, gcl = bj + hc - 3;
        float4 v = make_float4(0.f, 0.f, 0.f, 0.f);
        if ((unsigned)gr < H && (unsigned)gcl < W)
            v = *(const float4*)(gx + (((size_t)gr * W + gcl) * C + cbase + q * 4));
        __half2 h0 = __float22half2_rn(make_float2(v.x, v.y));
        __half2 h1 = __float22half2_rn(make_float2(v.z, v.w));
        uint2 st;
        st.x = *(uint32_t*)&h0;
        st.y = *(uint32_t*)&h1;
        *(uint2*)(xs2 + q * XCHUNK2 + (hr * 24 + hc) * 2) = st;
    }
}

// ---- compute one pass: 1 row x 8 cols x 4 ch, software-pipelined rows ----
__device__ __forceinline__ void compute_pass(const uint32_t* __restrict__ xs2,
                                             const float* __restrict__ w3,
                                             const float* __restrict__ inv,
                                             float* __restrict__ gout,
                                             int bi, int bj, int cbase,
                                             int row, int j0, int chg) {
    ull acc[8][2];
    #pragma unroll
    for (int j = 0; j < 8; ++j) { acc[j][0] = 0ull; acc[j][1] = 0ull; }

    const uint32_t* xb   = xs2 + chg * XCHUNK2 + j0 * 2;
    const float*    wrow = w3 + row * WISTRIDE + j0 * 64;

    // prefetch first 8 raw positions of halo row 0
    uint2 raw[8];
    {
        const uint2* xp = (const uint2*)(xb + row * XROWU);
        #pragma unroll
        for (int t = 0; t < 8; ++t) raw[t] = xp[t];
    }

    #pragma unroll
    for (int p = 0; p < 8; ++p) {
        const uint2* xp = (const uint2*)(xb + (row + p) * XROWU);
        ull xf[15][2];
        #pragma unroll
        for (int t = 0; t < 8; ++t) {
            float2 f01 = __half22float2(*(__half2*)&raw[t].x);
            float2 f23 = __half22float2(*(__half2*)&raw[t].y);
            xf[t][0] = pack2(f01.x, f01.y);
            xf[t][1] = pack2(f23.x, f23.y);
        }
        #pragma unroll
        for (int t = 8; t < 15; ++t) {
            uint2 h = xp[t];
            float2 f01 = __half22float2(*(__half2*)&h.x);
            float2 f23 = __half22float2(*(__half2*)&h.y);
            xf[t][0] = pack2(f01.x, f01.y);
            xf[t][1] = pack2(f23.x, f23.y);
        }
        if (p < 7) {   // prefetch next row's first 8 (hidden by fma block)
            const uint2* xn = (const uint2*)(xb + (row + p + 1) * XROWU);
            #pragma unroll
            for (int t = 0; t < 8; ++t) raw[t] = xn[t];
        }
        #pragma unroll
        for (int j = 0; j < 8; ++j) {
            #pragma unroll
            for (int qg = 0; qg < 2; ++qg) {
                float4 w4 = *(const float4*)(wrow + j * 64 + p * 8 + qg * 4);
                const int t0 = j + qg * 4;
                ull w0 = pack2(w4.x, w4.x);
                ull w1 = pack2(w4.y, w4.y);
                ull w2 = pack2(w4.z, w4.z);
                ull w3p = pack2(w4.w, w4.w);
                fma2(acc[j][0], xf[t0 + 0][0], w0);
                fma2(acc[j][1], xf[t0 + 0][1], w0);
                fma2(acc[j][0], xf[t0 + 1][0], w1);
                fma2(acc[j][1], xf[t0 + 1][1], w1);
                fma2(acc[j][0], xf[t0 + 2][0], w2);
                fma2(acc[j][1], xf[t0 + 2][1], w2);
                fma2(acc[j][0], xf[t0 + 3][0], w3p);
                fma2(acc[j][1], xf[t0 + 3][1], w3p);
            }
        }
    }

    // ---- normalize + store (8 chg lanes -> 128 B contiguous per (row,j)) ----
    #pragma unroll
    for (int j = 0; j < 8; ++j) {
        float s = inv[row * 16 + j0 + j];
        float2 a0 = unpack2(acc[j][0]);
        float2 a1 = unpack2(acc[j][1]);
        float4 v = make_float4(a0.x * s, a0.y * s, a1.x * s, a1.y * s);
        *(float4*)(gout + (((size_t)(bi + row) * W + (bj + j0 + j)) * C
                           + cbase + chg * 4)) = v;
    }
}

__global__ __launch_bounds__(512, 1) void cell_att_kernel(
    const float* __restrict__ gx,   // [H][W][C]
    const float* __restrict__ gw,   // [H][W][64]
    const float* __restrict__ gc,   // [H][W]
    float* __restrict__ gout)       // [H][W][C]
{
    extern __shared__ float smem[];
    float*    w3  = smem;                        // fp32 weights
    uint32_t* xs2 = (uint32_t*)(w3 + W3_FLOATS); // fp16 x halo
    float*    ch  = (float*)(xs2 + XS_U32);      // 39x23 cnts halo (fp32)
    float*    inv = ch + HR * HC;                // 512 per-pixel normalizers

    const int tid = threadIdx.x;
    const int chg = tid & 7;            // channel quad (4 ch)
    const int row = (tid >> 3) & 31;    // 0..31
    const int jg  = tid >> 8;           // 0 or 1
    const int j0  = jg * 8;
    const int bi = blockIdx.y * TI, bj = blockIdx.x * TJ;

    // ---- stage weights (cp.async, natural layout) + cnts halo ----
    #pragma unroll 8
    for (int u = tid; u < 512 * 16; u += 512) {
        int quad = u & 15, px = u >> 4;
        int il = px >> 4, jl = px & 15;    // il 0..31, jl 0..15
        const float* src = gw + ((size_t)(bi + il) * W + (bj + jl)) * 64 + quad * 4;
        cp_async16(w3 + il * WISTRIDE + jl * 64 + quad * 4, src);
    }
    for (int u = tid; u < HR * HC; u += 512) {
        int hr = u / HC, hc = u - hr * HC;
        int gr = bi + hr - 3, gcl = bj + hc - 3;
        bool ok = ((unsigned)gr < H) && ((unsigned)gcl < W);
        const float* src = ok ? gc + (size_t)gr * W + gcl : gc;
        cp_async4(ch + u, src, ok);
    }
    cp_commit();

    // ---- stage x pass 0 (LDGs fly alongside the cp.async group) ----
    stage_x(xs2, gx, bi, bj, 0, tid);

    cp_wait<0>();
    __syncthreads();                    // w3, ch, xs2(pass0) all visible

    // ---- normalizer: inv = 1/(att(cnts)+1e-6), one pixel per thread ----
    {
        int il = tid >> 4, jl = tid & 15;   // il 0..31
        const float* wpx = w3 + il * WISTRIDE + jl * 64;
        float s = 0.f;
        #pragma unroll
        for (int p = 0; p < 8; ++p)
            #pragma unroll
            for (int q = 0; q < 8; ++q)
                s += ch[(il + p) * HC + (jl + q)] * wpx[p * 8 + q];
        inv[tid] = 1.0f / (s + 1e-6f);
    }
    __syncthreads();                    // inv visible

    compute_pass(xs2, w3, inv, gout, bi, bj, 0, row, j0, chg);

    #pragma unroll 1
    for (int pass = 1; pass < 4; ++pass) {
        __syncthreads();                // everyone done reading xs2
        stage_x(xs2, gx, bi, bj, pass, tid);
        __syncthreads();                // new xs2 visible
        compute_pass(xs2, w3, inv, gout, bi, bj, pass * 32, row, j0, chg);
    }
}

extern "C" void kernel_launch(void* const* d_in, const int* in_sizes, int n_in,
                              void* d_out, int out_size) {
    const float* x0 = (const float*)d_in[0];
    const float* w  = (const float*)d_in[1];
    const float* c  = (const float*)d_in[2];
    float* out      = (float*)d_out;
    cudaFuncSetAttribute(cell_att_kernel,
                         cudaFuncAttributeMaxDynamicSharedMemorySize, SMEM_BYTES);
    dim3 grid(W / TJ, H / TI);
    cell_att_kernel<<<grid, 512, SMEM_BYTES>>>(x0, w, c, out);
}